// round 9
// baseline (speedup 1.0000x reference)
#include <cuda_runtime.h>
#include <cuda_bf16.h>
#include <cuda_fp16.h>
#include <math.h>
#include <stdint.h>

typedef unsigned long long u64;

#define B_TOTAL 8192
#define INDIM   784
#define NN      30
#define ND      20
#define NOUT    10
#define DK      16

// ---- k1 HMMA tiling ----
#define GNETS   6
#define NGRP    5
#define NT      15
#define KS49    49
#define NBAND   (B_TOTAL / 16)
#define HSTR    121

// ---- k2a tiling ----
#define RBA   8
#define UPAD  12

// ---- k2b tiling ----
#define RB2   16
#define T2B   256
#define PROW  (NOUT * NN * DK)    // 4800 halfs per batch row

// ---- device scratch ----
__device__ float  g_u [(size_t)B_TOTAL * NN * ND];
__device__ __half g_ph[(size_t)B_TOTAL * PROW];          // priors fp16 (78.6MB, L2-resident)
__device__ uint4  g_xhf[(size_t)NBAND * KS49 * 32];
__device__ uint4  g_xlf[(size_t)NBAND * KS49 * 32];
__device__ uint2  g_wbhf[(size_t)NGRP * KS49 * NT * 32];
__device__ uint2  g_wblf[(size_t)NGRP * KS49 * NT * 32];

// ---------------------------------------------------------------------------
// helpers
// ---------------------------------------------------------------------------
__device__ __forceinline__ uint32_t pbf2(float a, float b) {
    __nv_bfloat162 t = __floats2bfloat162_rn(a, b);
    return *(uint32_t*)&t;
}
__device__ __forceinline__ void split2(float v, float& h, float& l) {
    __nv_bfloat16 hb = __float2bfloat16(v);
    h = __bfloat162float(hb);
    l = v - h;
}
#define MMA_BF16(d, a, b) \
    asm volatile("mma.sync.aligned.m16n8k16.row.col.f32.bf16.bf16.f32 " \
        "{%0,%1,%2,%3}, {%4,%5,%6,%7}, {%8,%9}, {%0,%1,%2,%3};" \
        : "+f"((d)[0]), "+f"((d)[1]), "+f"((d)[2]), "+f"((d)[3]) \
        : "r"((a).x), "r"((a).y), "r"((a).z), "r"((a).w), \
          "r"((b).x), "r"((b).y))

__device__ __forceinline__ u64 pack2(float lo, float hi) {
    u64 r; asm("mov.b64 %0, {%1,%2};" : "=l"(r) : "f"(lo), "f"(hi)); return r;
}
__device__ __forceinline__ void unpack2(u64 v, float& lo, float& hi) {
    asm("mov.b64 {%0,%1}, %2;" : "=f"(lo), "=f"(hi) : "l"(v));
}
__device__ __forceinline__ void fma2(u64& d, u64 a, u64 b) {
    asm("fma.rn.f32x2 %0, %1, %2, %0;" : "+l"(d) : "l"(a), "l"(b));
}

// ---------------------------------------------------------------------------
// k0x: pack x into m16n8k16 A-fragment layout, split bf16 hi/lo
// ---------------------------------------------------------------------------
__global__ __launch_bounds__(256) void k0_pack_x(const float* __restrict__ x) {
    int gid = blockIdx.x * 256 + threadIdx.x;
    if (gid >= NBAND * KS49 * 32) return;
    int lane = gid & 31;
    int t    = gid >> 5;
    int ks   = t % KS49;
    int band = t / KS49;

    int r0 = band * 16 + (lane >> 2);
    int c0 = ks * 16 + (lane & 3) * 2;
    const float* p0 = x + (size_t)r0 * INDIM + c0;
    const float* p1 = p0 + 8 * INDIM;

    float v[8] = { p0[0], p0[1], p1[0], p1[1], p0[8], p0[9], p1[8], p1[9] };
    float h[8], l[8];
    #pragma unroll
    for (int i = 0; i < 8; i++) split2(v[i], h[i], l[i]);

    g_xhf[gid] = make_uint4(pbf2(h[0], h[1]), pbf2(h[2], h[3]),
                            pbf2(h[4], h[5]), pbf2(h[6], h[7]));
    g_xlf[gid] = make_uint4(pbf2(l[0], l[1]), pbf2(l[2], l[3]),
                            pbf2(l[4], l[5]), pbf2(l[6], l[7]));
}

// ---------------------------------------------------------------------------
// k0w: pack W1 into n8k16 B-fragment layout (col-major), hi/lo
// ---------------------------------------------------------------------------
__global__ __launch_bounds__(256) void k0_pack_w(const float* __restrict__ W1) {
    int gid = blockIdx.x * 256 + threadIdx.x;
    if (gid >= NGRP * KS49 * NT * 32) return;
    int lane = gid & 31;
    int t    = (gid >> 5) % NT;
    int ks   = ((gid >> 5) / NT) % KS49;
    int grp  = (gid >> 5) / (NT * KS49);

    int col = t * 8 + (lane >> 2);
    int net = grp * GNETS + col / ND;
    int c   = col % ND;
    int k0  = ks * 16 + (lane & 3) * 2;

    const float* wp = W1 + ((size_t)net * INDIM + k0) * ND + c;
    float v[4] = { wp[0], wp[ND], wp[8 * ND], wp[9 * ND] };
    float h[4], l[4];
    #pragma unroll
    for (int i = 0; i < 4; i++) split2(v[i], h[i], l[i]);

    g_wbhf[gid] = make_uint2(pbf2(h[0], h[1]), pbf2(h[2], h[3]));
    g_wblf[gid] = make_uint2(pbf2(l[0], l[1]), pbf2(l[2], l[3]));
}

// ---------------------------------------------------------------------------
// k1: HMMA split-bf16 GEMM1 + fused GEMM2/squash epilogue (frozen, verified)
// ---------------------------------------------------------------------------
__global__ __launch_bounds__(256, 2) void k1_mma(
    const float* __restrict__ b1,
    const float* __restrict__ W2,
    const float* __restrict__ b2)
{
    extern __shared__ __align__(16) float sm[];
    float* hs  = sm;
    float* ws2 = sm + 128 * HSTR;
    float* b1s = ws2 + GNETS * 400;
    float* b2s = b1s + GNETS * ND;

    const int tid  = threadIdx.x;
    const int w    = tid >> 5;
    const int lane = tid & 31;
    const int grp  = blockIdx.y;
    const int row0 = blockIdx.x * 128;

    for (int it = tid; it < GNETS * 400; it += 256)
        ws2[it] = W2[(size_t)(grp * GNETS) * 400 + it];
    if (tid < GNETS * ND) {
        b1s[tid] = b1[grp * GNETS * ND + tid];
        b2s[tid] = b2[grp * GNETS * ND + tid];
    }

    float acc[NT][4];
    #pragma unroll
    for (int t = 0; t < NT; t++)
        #pragma unroll
        for (int i = 0; i < 4; i++) acc[t][i] = 0.f;

    const int band = blockIdx.x * 8 + w;
    const uint4* pah = g_xhf + (size_t)band * KS49 * 32 + lane;
    const uint4* pal = g_xlf + (size_t)band * KS49 * 32 + lane;
    const uint2* pbh = g_wbhf + (size_t)grp * KS49 * NT * 32 + lane;
    const uint2* pbl = g_wblf + (size_t)grp * KS49 * NT * 32 + lane;

    uint4 ah = pah[0];
    uint4 al = pal[0];
    for (int ks = 0; ks < KS49; ks++) {
        uint4 ah_n, al_n;
        if (ks + 1 < KS49) {
            ah_n = pah[(ks + 1) * 32];
            al_n = pal[(ks + 1) * 32];
        }
        const uint2* bh = pbh + ks * NT * 32;
        const uint2* bl = pbl + ks * NT * 32;
        #pragma unroll
        for (int t = 0; t < NT; t++) {
            uint2 vh = bh[t * 32];
            uint2 vl = bl[t * 32];
            MMA_BF16(acc[t], ah, vh);
            MMA_BF16(acc[t], al, vh);
            MMA_BF16(acc[t], ah, vl);
        }
        ah = ah_n; al = al_n;
    }

    {
        const int rlo = w * 16 + (lane >> 2);
        const int cb  = (lane & 3) * 2;
        #pragma unroll
        for (int t = 0; t < NT; t++) {
            int col = t * 8 + cb;
            hs[rlo * HSTR + col]           = acc[t][0];
            hs[rlo * HSTR + col + 1]       = acc[t][1];
            hs[(rlo + 8) * HSTR + col]     = acc[t][2];
            hs[(rlo + 8) * HSTR + col + 1] = acc[t][3];
        }
    }
    __syncthreads();

    for (int task = tid; task < 128 * GNETS; task += 256) {
        const int row = task / GNETS;
        const int g   = task % GNETS;
        const int net = grp * GNETS + g;
        float h[ND];
        #pragma unroll
        for (int c = 0; c < ND; c++) {
            float v = hs[row * HSTR + g * ND + c] + b1s[g * ND + c];
            h[c] = v > 0.f ? v : 0.f;
        }
        float h2[ND];
        float sq = 0.f;
        #pragma unroll
        for (int e = 0; e < ND; e++) {
            float s = b2s[g * ND + e];
            #pragma unroll
            for (int d = 0; d < ND; d++) s += h[d] * ws2[g * 400 + d * ND + e];
            s = s > 0.f ? s : 0.f;
            h2[e] = s;
            sq += s * s;
        }
        float scale = (sq / (1.f + sq)) / sqrtf(sq);
        float* up = g_u + (size_t)(row0 + row) * (NN * ND) + net * ND;
        #pragma unroll
        for (int e4 = 0; e4 < 5; e4++)
            *(float4*)(up + e4 * 4) = make_float4(scale * h2[e4*4],   scale * h2[e4*4+1],
                                                  scale * h2[e4*4+2], scale * h2[e4*4+3]);
    }
}

// ---------------------------------------------------------------------------
// k2a: priors = u @ route, written to g_ph (fp16, [b][o][n][k]) via smem stage
// grid = B/8, block 640. Compute identical to verified fused version.
// ---------------------------------------------------------------------------
__global__ __launch_bounds__(640, 1) void k2a_priors(
    const float* __restrict__ route)      // [10, 30, 20, 16]
{
    extern __shared__ __align__(16) float sm[];
    float*  u_s = sm;                               // [600][UPAD] 28.8KB
    __half* p_h = (__half*)(sm + 600 * UPAD);       // [8][10][30][16] 76.8KB

    const int tid = threadIdx.x;
    const int r0  = blockIdx.x * RBA;

    // load u for 8 rows, transposed [c][row]
    for (int it = tid; it < RBA * NN * ND; it += 640) {
        int r = it / (NN * ND);
        int c = it % (NN * ND);
        u_s[c * UPAD + r] = g_u[(size_t)(r0 + r) * (NN * ND) + c];
    }
    __syncthreads();

    if (tid < 600) {
        const int n  = tid / 20;
        const int oo = tid % 20;
        const int o  = oo >> 1;
        const int kg = oo & 1;

        u64 acc[4][8];
        #pragma unroll
        for (int i = 0; i < 4; i++)
            #pragma unroll
            for (int j = 0; j < 8; j++) acc[i][j] = 0ull;

        const float* rp = route + (size_t)((o * NN + n) * ND) * DK + kg * 8;
        const float* up = u_s + (n * ND) * UPAD;

        #pragma unroll 4
        for (int d = 0; d < ND; d++) {
            ulonglong2 ua = *(const ulonglong2*)(up + d * UPAD);
            ulonglong2 ub = *(const ulonglong2*)(up + d * UPAD + 4);
            u64 uv[4] = {ua.x, ua.y, ub.x, ub.y};
            float4 ra = *(const float4*)(rp + (size_t)d * DK);
            float4 rb = *(const float4*)(rp + (size_t)d * DK + 4);
            u64 wv[8] = {pack2(ra.x, ra.x), pack2(ra.y, ra.y),
                         pack2(ra.z, ra.z), pack2(ra.w, ra.w),
                         pack2(rb.x, rb.x), pack2(rb.y, rb.y),
                         pack2(rb.z, rb.z), pack2(rb.w, rb.w)};
            #pragma unroll
            for (int i = 0; i < 4; i++)
                #pragma unroll
                for (int j = 0; j < 8; j++)
                    fma2(acc[i][j], uv[i], wv[j]);
        }

        // acc -> fp16 smem stage  [r][o][n][k]
        #pragma unroll
        for (int i = 0; i < 4; i++)
            #pragma unroll
            for (int j = 0; j < 8; j++) {
                float lo, hi; unpack2(acc[i][j], lo, hi);
                int kk = kg * 8 + j;
                p_h[(((2*i    ) * NOUT + o) * NN + n) * DK + kk] = __float2half_rn(lo);
                p_h[(((2*i + 1) * NOUT + o) * NN + n) * DK + kk] = __float2half_rn(hi);
            }
    }
    __syncthreads();

    // coalesced copy: smem [8][4800] halfs -> gmem rows r0..r0+7 (contiguous)
    uint4* dst = (uint4*)(g_ph + (size_t)r0 * PROW);
    const uint4* src = (const uint4*)p_h;
    for (int it = tid; it < RBA * PROW / 8; it += 640)
        dst[it] = src[it];
}

// ---------------------------------------------------------------------------
// k2b: dynamic routing, streaming fp16 priors from L2.
// grid = B/16, block 256, 49.3KB smem -> 4 blocks/SM.
// ---------------------------------------------------------------------------
__global__ __launch_bounds__(T2B) void k2b_route(float* __restrict__ out) {
    extern __shared__ __align__(16) float sm[];
    float* l_s  = sm;                               // [16][10][30]
    float* pr_s = l_s + RB2 * NOUT * NN;            // [16][10][30]
    float* v_s  = pr_s + RB2 * NOUT * NN;           // [16][10][16]
    float* sc_s = v_s + RB2 * NOUT * DK;            // [16][10]

    const int tid = threadIdx.x;
    const int r0  = blockIdx.x * RB2;
    const __half* P = g_ph + (size_t)r0 * PROW;

    for (int iter = 0; iter < 3; iter++) {
        if (iter > 0) {
            // softmax over o, per (r, n)
            for (int it = tid; it < RB2 * NN; it += T2B) {
                int r = it / NN, n = it % NN;
                float l[NOUT];
                float mx = -1e30f;
                #pragma unroll
                for (int o = 0; o < NOUT; o++) {
                    l[o] = l_s[(r * NOUT + o) * NN + n];
                    mx = fmaxf(mx, l[o]);
                }
                float ssum = 0.f;
                #pragma unroll
                for (int o = 0; o < NOUT; o++) { l[o] = expf(l[o] - mx); ssum += l[o]; }
                float inv = 1.f / ssum;
                #pragma unroll
                for (int o = 0; o < NOUT; o++)
                    pr_s[(r * NOUT + o) * NN + n] = l[o] * inv;
            }
            __syncthreads();
        }

        // s-pass: item = (r, o, khalf); accumulate 8 k-values over n
        for (int it = tid; it < RB2 * NOUT * 2; it += T2B) {
            int kh = it & 1;
            int ro = it >> 1;               // r*10 + o
            const __half* pp = P + (size_t)ro * (NN * DK) + kh * 8;
            float s8[8] = {0,0,0,0,0,0,0,0};
            #pragma unroll 2
            for (int n = 0; n < NN; n++) {
                uint4 q = *(const uint4*)(pp + n * DK);
                __half2* hx = (__half2*)&q;
                float w = (iter == 0) ? 1.f : pr_s[ro * NN + n];
                #pragma unroll
                for (int p = 0; p < 4; p++) {
                    float2 f = __half22float2(hx[p]);
                    s8[2*p]   += w * f.x;
                    s8[2*p+1] += w * f.y;
                }
            }
            float mul = (iter == 0) ? 0.1f : 1.f;
            #pragma unroll
            for (int j = 0; j < 8; j++) v_s[ro * DK + kh * 8 + j] = s8[j] * mul;
        }
        __syncthreads();

        // squash per (r,o): scale the 16-vector in place
        for (int it = tid; it < RB2 * NOUT; it += T2B) {
            float* vp = v_s + it * DK;
            float sq = 0.f;
            #pragma unroll
            for (int k = 0; k < DK; k++) sq += vp[k] * vp[k];
            float scale = (sq / (1.f + sq)) / sqrtf(sq);
            #pragma unroll
            for (int k = 0; k < DK; k++) vp[k] *= scale;
            sc_s[it] = scale;   // unused, keeps layout
        }
        __syncthreads();

        if (iter < 2) {
            // logits: item = (r, o, n); dot over k (16 contiguous halfs)
            for (int it = tid; it < RB2 * NOUT * NN; it += T2B) {
                int n  = it % NN;
                int ro = it / NN;
                const __half* pp = P + (size_t)ro * (NN * DK) + n * DK;
                const float* vp = v_s + ro * DK;
                uint4 q0 = *(const uint4*)pp;
                uint4 q1 = *(const uint4*)(pp + 8);
                __half2* h0 = (__half2*)&q0;
                __half2* h1 = (__half2*)&q1;
                float s = 0.f;
                #pragma unroll
                for (int p = 0; p < 4; p++) {
                    float2 f0 = __half22float2(h0[p]);
                    float2 f1 = __half22float2(h1[p]);
                    s += f0.x * vp[2*p]     + f0.y * vp[2*p + 1];
                    s += f1.x * vp[8 + 2*p] + f1.y * vp[8 + 2*p + 1];
                }
                float nl = (iter == 0) ? s : (l_s[(ro) * NN + n] + s);
                l_s[ro * NN + n] = nl;
            }
            __syncthreads();
        }
    }

    // write output [B,10,16]
    for (int it = tid; it < RB2 * NOUT * DK; it += T2B) {
        int r = it / (NOUT * DK);
        out[(size_t)(r0 + r) * (NOUT * DK) + (it % (NOUT * DK))] = v_s[it];
    }
}

// ---------------------------------------------------------------------------
extern "C" void kernel_launch(void* const* d_in, const int* in_sizes, int n_in,
                              void* d_out, int out_size)
{
    const float* x     = (const float*)d_in[0];
    const float* W1    = (const float*)d_in[1];
    const float* b1    = (const float*)d_in[2];
    const float* W2    = (const float*)d_in[3];
    const float* b2    = (const float*)d_in[4];
    const float* route = (const float*)d_in[5];
    float* out = (float*)d_out;

    // pack inputs into HMMA fragment layout (bf16 hi/lo)
    k0_pack_x<<<(NBAND * KS49 * 32 + 255) / 256, 256>>>(x);
    k0_pack_w<<<(NGRP * KS49 * NT * 32 + 255) / 256, 256>>>(W1);

    // tensor-core GEMM1 + fused epilogue
    const int smem1 = (128 * HSTR + GNETS * 400 + 2 * GNETS * ND) * (int)sizeof(float);
    cudaFuncSetAttribute(k1_mma, cudaFuncAttributeMaxDynamicSharedMemorySize, smem1);
    dim3 g1(B_TOTAL / 128, NGRP);
    k1_mma<<<g1, 256, smem1>>>(b1, W2, b2);

    // priors -> fp16 gmem (L2-resident)
    const int smem2a = 600 * UPAD * (int)sizeof(float)
                     + RBA * NOUT * NN * DK * (int)sizeof(__half);   // 105,600 B
    cudaFuncSetAttribute(k2a_priors, cudaFuncAttributeMaxDynamicSharedMemorySize, smem2a);
    k2a_priors<<<B_TOTAL / RBA, 640, smem2a>>>(route);

    // routing (streams priors from L2)
    const int smem2b = (2 * RB2 * NOUT * NN + RB2 * NOUT * DK + RB2 * NOUT)
                     * (int)sizeof(float);                           // 49,280 B
    cudaFuncSetAttribute(k2b_route, cudaFuncAttributeMaxDynamicSharedMemorySize, smem2b);
    k2b_route<<<B_TOTAL / RB2, T2B, smem2b>>>(out);
}

// round 10
// speedup vs baseline: 1.1960x; 1.1960x over previous
#include <cuda_runtime.h>
#include <cuda_bf16.h>
#include <cuda_fp16.h>
#include <math.h>
#include <stdint.h>

typedef unsigned long long u64;

#define B_TOTAL 8192
#define INDIM   784
#define NN      30
#define ND      20
#define NOUT    10
#define DK      16

// ---- k1 HMMA tiling ----
#define GNETS   6
#define NGRP    5
#define NT      15
#define KS49    49
#define NBAND   (B_TOTAL / 16)
#define HSTR    121

// ---- k2 tiling ----
#define RB    8
#define T2    640
#define UPAD  12

// ---- device scratch ----
__device__ float g_u[(size_t)B_TOTAL * NN * ND];
__device__ uint4 g_xhf[(size_t)NBAND * KS49 * 32];
__device__ uint4 g_xlf[(size_t)NBAND * KS49 * 32];
__device__ uint2 g_wbhf[(size_t)NGRP * KS49 * NT * 32];
__device__ uint2 g_wblf[(size_t)NGRP * KS49 * NT * 32];

// ---------------------------------------------------------------------------
// helpers
// ---------------------------------------------------------------------------
__device__ __forceinline__ uint32_t pbf2(float a, float b) {
    __nv_bfloat162 t = __floats2bfloat162_rn(a, b);
    return *(uint32_t*)&t;
}
__device__ __forceinline__ void split2(float v, float& h, float& l) {
    __nv_bfloat16 hb = __float2bfloat16(v);
    h = __bfloat162float(hb);
    l = v - h;
}
#define MMA_BF16(d, a, b) \
    asm volatile("mma.sync.aligned.m16n8k16.row.col.f32.bf16.bf16.f32 " \
        "{%0,%1,%2,%3}, {%4,%5,%6,%7}, {%8,%9}, {%0,%1,%2,%3};" \
        : "+f"((d)[0]), "+f"((d)[1]), "+f"((d)[2]), "+f"((d)[3]) \
        : "r"((a).x), "r"((a).y), "r"((a).z), "r"((a).w), \
          "r"((b).x), "r"((b).y))

__device__ __forceinline__ u64 pack2(float lo, float hi) {
    u64 r; asm("mov.b64 %0, {%1,%2};" : "=l"(r) : "f"(lo), "f"(hi)); return r;
}
__device__ __forceinline__ void unpack2(u64 v, float& lo, float& hi) {
    asm("mov.b64 {%0,%1}, %2;" : "=f"(lo), "=f"(hi) : "l"(v));
}
__device__ __forceinline__ void fma2(u64& d, u64 a, u64 b) {
    asm("fma.rn.f32x2 %0, %1, %2, %0;" : "+l"(d) : "l"(a), "l"(b));
}

// ---------------------------------------------------------------------------
// k0x: pack x into m16n8k16 A-fragment layout, split bf16 hi/lo
// ---------------------------------------------------------------------------
__global__ __launch_bounds__(256) void k0_pack_x(const float* __restrict__ x) {
    int gid = blockIdx.x * 256 + threadIdx.x;
    if (gid >= NBAND * KS49 * 32) return;
    int lane = gid & 31;
    int t    = gid >> 5;
    int ks   = t % KS49;
    int band = t / KS49;

    int r0 = band * 16 + (lane >> 2);
    int c0 = ks * 16 + (lane & 3) * 2;
    const float* p0 = x + (size_t)r0 * INDIM + c0;
    const float* p1 = p0 + 8 * INDIM;

    float v[8] = { p0[0], p0[1], p1[0], p1[1], p0[8], p0[9], p1[8], p1[9] };
    float h[8], l[8];
    #pragma unroll
    for (int i = 0; i < 8; i++) split2(v[i], h[i], l[i]);

    g_xhf[gid] = make_uint4(pbf2(h[0], h[1]), pbf2(h[2], h[3]),
                            pbf2(h[4], h[5]), pbf2(h[6], h[7]));
    g_xlf[gid] = make_uint4(pbf2(l[0], l[1]), pbf2(l[2], l[3]),
                            pbf2(l[4], l[5]), pbf2(l[6], l[7]));
}

// ---------------------------------------------------------------------------
// k0w: pack W1 into n8k16 B-fragment layout (col-major), hi/lo
// ---------------------------------------------------------------------------
__global__ __launch_bounds__(256) void k0_pack_w(const float* __restrict__ W1) {
    int gid = blockIdx.x * 256 + threadIdx.x;
    if (gid >= NGRP * KS49 * NT * 32) return;
    int lane = gid & 31;
    int t    = (gid >> 5) % NT;
    int ks   = ((gid >> 5) / NT) % KS49;
    int grp  = (gid >> 5) / (NT * KS49);

    int col = t * 8 + (lane >> 2);
    int net = grp * GNETS + col / ND;
    int c   = col % ND;
    int k0  = ks * 16 + (lane & 3) * 2;

    const float* wp = W1 + ((size_t)net * INDIM + k0) * ND + c;
    float v[4] = { wp[0], wp[ND], wp[8 * ND], wp[9 * ND] };
    float h[4], l[4];
    #pragma unroll
    for (int i = 0; i < 4; i++) split2(v[i], h[i], l[i]);

    g_wbhf[gid] = make_uint2(pbf2(h[0], h[1]), pbf2(h[2], h[3]));
    g_wblf[gid] = make_uint2(pbf2(l[0], l[1]), pbf2(l[2], l[3]));
}

// ---------------------------------------------------------------------------
// k1: HMMA split-bf16 GEMM1 + fused GEMM2/squash epilogue (frozen, verified)
// ---------------------------------------------------------------------------
__global__ __launch_bounds__(256, 2) void k1_mma(
    const float* __restrict__ b1,
    const float* __restrict__ W2,
    const float* __restrict__ b2)
{
    extern __shared__ __align__(16) float sm[];
    float* hs  = sm;
    float* ws2 = sm + 128 * HSTR;
    float* b1s = ws2 + GNETS * 400;
    float* b2s = b1s + GNETS * ND;

    const int tid  = threadIdx.x;
    const int w    = tid >> 5;
    const int lane = tid & 31;
    const int grp  = blockIdx.y;
    const int row0 = blockIdx.x * 128;

    for (int it = tid; it < GNETS * 400; it += 256)
        ws2[it] = W2[(size_t)(grp * GNETS) * 400 + it];
    if (tid < GNETS * ND) {
        b1s[tid] = b1[grp * GNETS * ND + tid];
        b2s[tid] = b2[grp * GNETS * ND + tid];
    }

    float acc[NT][4];
    #pragma unroll
    for (int t = 0; t < NT; t++)
        #pragma unroll
        for (int i = 0; i < 4; i++) acc[t][i] = 0.f;

    const int band = blockIdx.x * 8 + w;
    const uint4* pah = g_xhf + (size_t)band * KS49 * 32 + lane;
    const uint4* pal = g_xlf + (size_t)band * KS49 * 32 + lane;
    const uint2* pbh = g_wbhf + (size_t)grp * KS49 * NT * 32 + lane;
    const uint2* pbl = g_wblf + (size_t)grp * KS49 * NT * 32 + lane;

    uint4 ah = pah[0];
    uint4 al = pal[0];
    for (int ks = 0; ks < KS49; ks++) {
        uint4 ah_n, al_n;
        if (ks + 1 < KS49) {
            ah_n = pah[(ks + 1) * 32];
            al_n = pal[(ks + 1) * 32];
        }
        const uint2* bh = pbh + ks * NT * 32;
        const uint2* bl = pbl + ks * NT * 32;
        #pragma unroll
        for (int t = 0; t < NT; t++) {
            uint2 vh = bh[t * 32];
            uint2 vl = bl[t * 32];
            MMA_BF16(acc[t], ah, vh);
            MMA_BF16(acc[t], al, vh);
            MMA_BF16(acc[t], ah, vl);
        }
        ah = ah_n; al = al_n;
    }

    {
        const int rlo = w * 16 + (lane >> 2);
        const int cb  = (lane & 3) * 2;
        #pragma unroll
        for (int t = 0; t < NT; t++) {
            int col = t * 8 + cb;
            hs[rlo * HSTR + col]           = acc[t][0];
            hs[rlo * HSTR + col + 1]       = acc[t][1];
            hs[(rlo + 8) * HSTR + col]     = acc[t][2];
            hs[(rlo + 8) * HSTR + col + 1] = acc[t][3];
        }
    }
    __syncthreads();

    for (int task = tid; task < 128 * GNETS; task += 256) {
        const int row = task / GNETS;
        const int g   = task % GNETS;
        const int net = grp * GNETS + g;
        float h[ND];
        #pragma unroll
        for (int c = 0; c < ND; c++) {
            float v = hs[row * HSTR + g * ND + c] + b1s[g * ND + c];
            h[c] = v > 0.f ? v : 0.f;
        }
        float h2[ND];
        float sq = 0.f;
        #pragma unroll
        for (int e = 0; e < ND; e++) {
            float s = b2s[g * ND + e];
            #pragma unroll
            for (int d = 0; d < ND; d++) s += h[d] * ws2[g * 400 + d * ND + e];
            s = s > 0.f ? s : 0.f;
            h2[e] = s;
            sq += s * s;
        }
        float scale = (sq / (1.f + sq)) / sqrtf(sq);
        float* up = g_u + (size_t)(row0 + row) * (NN * ND) + net * ND;
        #pragma unroll
        for (int e4 = 0; e4 < 5; e4++)
            *(float4*)(up + e4 * 4) = make_float4(scale * h2[e4*4],   scale * h2[e4*4+1],
                                                  scale * h2[e4*4+2], scale * h2[e4*4+3]);
    }
}

// ---------------------------------------------------------------------------
// k2: fused priors + routing. Priors in fp16 smem [r][o][n][16] (vectorized),
// routing buffers overlay the u_s region. grid = B/8, block 640, 105.6KB smem.
// ---------------------------------------------------------------------------
__global__ __launch_bounds__(T2, 1) void k2_route(
    const float* __restrict__ route,  // [10, 30, 20, 16]
    float* __restrict__ out)          // [B, 10, 16]
{
    extern __shared__ __align__(16) char smraw[];
    float*  u_s = (float*)smraw;                       // [600][UPAD] (priors phase only)
    // overlay (valid after priors barrier):
    float*  l_s  = (float*)smraw;                      // [8][300]
    float*  pr_s = l_s + RB * NOUT * NN;               // [8][300]
    float*  v_s  = pr_s + RB * NOUT * NN;              // [8][160]
    __half* p_h  = (__half*)(smraw + 600 * UPAD * 4);  // [8][10][30][16] fp16

    const int tid = threadIdx.x;
    const int r0  = blockIdx.x * RB;

    // load u for 8 rows, transposed [c][row]
    for (int it = tid; it < RB * NN * ND; it += T2) {
        int r = it / (NN * ND);
        int c = it % (NN * ND);
        u_s[c * UPAD + r] = g_u[(size_t)(r0 + r) * (NN * ND) + c];
    }
    __syncthreads();

    // ---- priors: thread = (n, o, kg); verified compute, fp16 vector stores ----
    if (tid < 600) {
        const int n  = tid / 20;
        const int oo = tid % 20;
        const int o  = oo >> 1;
        const int kg = oo & 1;

        u64 acc[4][8];
        #pragma unroll
        for (int i = 0; i < 4; i++)
            #pragma unroll
            for (int j = 0; j < 8; j++) acc[i][j] = 0ull;

        const float* rp = route + (size_t)((o * NN + n) * ND) * DK + kg * 8;
        const float* up = u_s + (n * ND) * UPAD;

        #pragma unroll 4
        for (int d = 0; d < ND; d++) {
            ulonglong2 ua = *(const ulonglong2*)(up + d * UPAD);
            ulonglong2 ub = *(const ulonglong2*)(up + d * UPAD + 4);
            u64 uv[4] = {ua.x, ua.y, ub.x, ub.y};
            float4 ra = *(const float4*)(rp + (size_t)d * DK);
            float4 rb = *(const float4*)(rp + (size_t)d * DK + 4);
            u64 wv[8] = {pack2(ra.x, ra.x), pack2(ra.y, ra.y),
                         pack2(ra.z, ra.z), pack2(ra.w, ra.w),
                         pack2(rb.x, rb.x), pack2(rb.y, rb.y),
                         pack2(rb.z, rb.z), pack2(rb.w, rb.w)};
            #pragma unroll
            for (int i = 0; i < 4; i++)
                #pragma unroll
                for (int j = 0; j < 8; j++)
                    fma2(acc[i][j], uv[i], wv[j]);
        }

        // acc -> fp16 stores: per row-pair, pack 8 k-values into one uint4
        #pragma unroll
        for (int i = 0; i < 4; i++) {
            float lo[8], hi[8];
            #pragma unroll
            for (int j = 0; j < 8; j++) unpack2(acc[i][j], lo[j], hi[j]);
            uint4 qlo, qhi;
            __half2* a = (__half2*)&qlo;
            __half2* b = (__half2*)&qhi;
            #pragma unroll
            for (int p = 0; p < 4; p++) {
                a[p] = __floats2half2_rn(lo[2*p], lo[2*p + 1]);
                b[p] = __floats2half2_rn(hi[2*p], hi[2*p + 1]);
            }
            *(uint4*)&p_h[((((2*i    ) * NOUT + o) * NN + n) * DK) + kg * 8] = qlo;
            *(uint4*)&p_h[((((2*i + 1) * NOUT + o) * NN + n) * DK) + kg * 8] = qhi;
        }
    }
    __syncthreads();   // also retires all u_s reads before overlay writes

    // ---- dynamic routing, 3 iterations (fp16 priors, vectorized) ----
    for (int iter = 0; iter < 3; iter++) {
        if (iter > 0) {
            // softmax over o, per (r, n)
            if (tid < RB * NN) {
                int r = tid / NN, n = tid % NN;
                float l[NOUT];
                float mx = -1e30f;
                #pragma unroll
                for (int o = 0; o < NOUT; o++) {
                    l[o] = l_s[(r * NOUT + o) * NN + n];
                    mx = fmaxf(mx, l[o]);
                }
                float ssum = 0.f;
                #pragma unroll
                for (int o = 0; o < NOUT; o++) { l[o] = expf(l[o] - mx); ssum += l[o]; }
                float inv = 1.f / ssum;
                #pragma unroll
                for (int o = 0; o < NOUT; o++)
                    pr_s[(r * NOUT + o) * NN + n] = l[o] * inv;
            }
            __syncthreads();
        }

        // s-pass: item = (ro, khalf); 8 k-values accumulated over n
        if (tid < RB * NOUT * 2) {
            int kh = tid & 1;
            int ro = tid >> 1;
            const __half* pp = p_h + ro * (NN * DK) + kh * 8;
            float s8[8] = {0,0,0,0,0,0,0,0};
            #pragma unroll 5
            for (int n = 0; n < NN; n++) {
                uint4 q = *(const uint4*)(pp + n * DK);
                __half2* hx = (__half2*)&q;
                float w = (iter == 0) ? 1.f : pr_s[ro * NN + n];
                #pragma unroll
                for (int p = 0; p < 4; p++) {
                    float2 f = __half22float2(hx[p]);
                    s8[2*p]   += w * f.x;
                    s8[2*p+1] += w * f.y;
                }
            }
            float mul = (iter == 0) ? 0.1f : 1.f;
            #pragma unroll
            for (int j = 0; j < 8; j++) v_s[ro * DK + kh * 8 + j] = s8[j] * mul;
        }
        __syncthreads();

        // squash per (r,o): scale 16-vector in place
        if (tid < RB * NOUT) {
            float* vp = v_s + tid * DK;
            float sq = 0.f;
            #pragma unroll
            for (int k = 0; k < DK; k++) sq += vp[k] * vp[k];
            float scale = (sq / (1.f + sq)) / sqrtf(sq);
            #pragma unroll
            for (int k = 0; k < DK; k++) vp[k] *= scale;
        }
        __syncthreads();

        if (iter < 2) {
            // logits: item = (r,o,n); dot over 16 contiguous fp16 k-values
            for (int it = tid; it < RB * NOUT * NN; it += T2) {
                int n  = it % NN;
                int ro = it / NN;
                const __half* pp = p_h + ro * (NN * DK) + n * DK;
                const float* vp = v_s + ro * DK;
                uint4 q0 = *(const uint4*)pp;
                uint4 q1 = *(const uint4*)(pp + 8);
                __half2* h0 = (__half2*)&q0;
                __half2* h1 = (__half2*)&q1;
                float s = 0.f;
                #pragma unroll
                for (int p = 0; p < 4; p++) {
                    float2 f0 = __half22float2(h0[p]);
                    float2 f1 = __half22float2(h1[p]);
                    s += f0.x * vp[2*p]     + f0.y * vp[2*p + 1];
                    s += f1.x * vp[8 + 2*p] + f1.y * vp[8 + 2*p + 1];
                }
                l_s[ro * NN + n] = (iter == 0) ? s : (l_s[ro * NN + n] + s);
            }
            __syncthreads();
        }
    }

    // write output [B,10,16]
    for (int it = tid; it < RB * NOUT * DK; it += T2) {
        int r = it / (NOUT * DK);
        out[(size_t)(r0 + r) * (NOUT * DK) + (it % (NOUT * DK))] = v_s[it];
    }
}

// ---------------------------------------------------------------------------
extern "C" void kernel_launch(void* const* d_in, const int* in_sizes, int n_in,
                              void* d_out, int out_size)
{
    const float* x     = (const float*)d_in[0];
    const float* W1    = (const float*)d_in[1];
    const float* b1    = (const float*)d_in[2];
    const float* W2    = (const float*)d_in[3];
    const float* b2    = (const float*)d_in[4];
    const float* route = (const float*)d_in[5];
    float* out = (float*)d_out;

    // pack inputs into HMMA fragment layout (bf16 hi/lo)
    k0_pack_x<<<(NBAND * KS49 * 32 + 255) / 256, 256>>>(x);
    k0_pack_w<<<(NGRP * KS49 * NT * 32 + 255) / 256, 256>>>(W1);

    // tensor-core GEMM1 + fused epilogue
    const int smem1 = (128 * HSTR + GNETS * 400 + 2 * GNETS * ND) * (int)sizeof(float);
    cudaFuncSetAttribute(k1_mma, cudaFuncAttributeMaxDynamicSharedMemorySize, smem1);
    dim3 g1(B_TOTAL / 128, NGRP);
    k1_mma<<<g1, 256, smem1>>>(b1, W2, b2);

    // fused priors + routing (fp16 priors in smem)
    const int smem2 = 600 * UPAD * (int)sizeof(float)
                    + RB * NOUT * NN * DK * (int)sizeof(__half);   // 105,600 B
    cudaFuncSetAttribute(k2_route, cudaFuncAttributeMaxDynamicSharedMemorySize, smem2);
    k2_route<<<B_TOTAL / RB, T2, smem2>>>(route, out);
}